// round 17
// baseline (speedup 1.0000x reference)
#include <cuda_runtime.h>
#include <stdint.h>
#include <math.h>

// Problem shape (fixed by the reference's setup_inputs)
#define Bn 4
#define Tn 8192
#define Dn 1024
#define D4n (Dn / 4)       // 256 float4 groups across channels
#define Ln 32              // chunk length along time
#define Cn (Tn / Ln)       // 256 chunks
#define CPL 8              // chunks per lane in the warp scan
#define TPB 256
#define GRID_CTAS 512          // 131072 threads; 4 CTAs/SM co-resident
#define NWARPS (GRID_CTAS * (TPB / 32))        // 4096 warps
#define NUNITS 8192                            // 32-item work units per phase
#define PERIOD ((unsigned long long)(NUNITS + NWARPS))   // exact tickets/launch

// Scan tables (double closed form, filled by table-duty threads after phase1):
__device__ float2 g_rL[Dn];      // r^L
__device__ float2 g_w [5][Dn];   // r^(8L * 2^s), s = 0..4

// Scratch (L2-resident): chunk-end and carry-in states, [c][b][k][d4]. 8 MB each.
__device__ float2 g_ends [Cn * Bn * 4 * D4n];
__device__ float2 g_carry[Cn * Bn * 4 * D4n];

// Self-resetting ticket barrier + monotonic work counters (no reset needed:
// each launch consumes exactly PERIOD tickets per counter).
__device__ unsigned g_bar[2];
__device__ unsigned long long g_work[2];

// ---------------------------------------------------------------------------
__device__ __forceinline__ void gsync(int slot)
{
    __syncthreads();
    if (threadIdx.x == 0) {
        __threadfence();                               // release prior writes
        unsigned ticket = atomicAdd(&g_bar[slot], 1u);
        unsigned target = (ticket / GRID_CTAS + 1u) * GRID_CTAS;
        volatile unsigned* bp = &g_bar[slot];
        while (*bp < target) { }
        __threadfence();                               // acquire
    }
    __syncthreads();
}

// fp32 per-step rotation r = exp(-|a|)(cos f, sin f) for this thread's 4 channels
__device__ __forceinline__ void calc_r(int d4,
                                       const float* __restrict__ decay,
                                       const float* __restrict__ freq,
                                       float rre[4], float rim[4])
{
    float4 a4 = ((const float4*)decay)[d4];
    float4 f4 = ((const float4*)freq)[d4];
    float av[4] = {a4.x, a4.y, a4.z, a4.w};
    float fv[4] = {f4.x, f4.y, f4.z, f4.w};
#pragma unroll
    for (int k = 0; k < 4; k++) {
        float g = expf(-fabsf(av[k]));
        float s, co;
        sincosf(fv[k], &s, &co);
        rre[k] = g * co;
        rim[k] = g * s;
    }
}

// ---------------------------------------------------------------------------
// Fused kernel with warp-level work stealing in the streaming phases:
//   phase1: steal 32-item units (item = [c][b][d4]); local recurrence -> ends
//   table duty (FP64 closed form) after phase1 grabs, before barrier
//   gsync | phase2: warp-parallel Kogge-Stone scan (static) | gsync
//   phase3: steal units in REVERSE order (hot chunks first); replay, write y
// ---------------------------------------------------------------------------
__global__ __launch_bounds__(TPB, 4)
void k_fused(const float4* __restrict__ x, float4* __restrict__ y,
             const float* __restrict__ decay, const float* __restrict__ freq)
{
    const int t    = blockIdx.x * TPB + threadIdx.x;
    const int lane = threadIdx.x & 31;

    // ---------------- phase 1: stolen local recurrences ----------------
    {
        unsigned long long tk;
        while (true) {
            if (lane == 0) tk = atomicAdd(&g_work[0], 1ULL);
            tk = __shfl_sync(0xFFFFFFFFu, tk, 0);
            unsigned u = (unsigned)(tk % PERIOD);
            if (u >= NUNITS) break;

            const int item = (int)u * 32 + lane;
            const int d4 = item & (D4n - 1);
            const int b  = (item >> 8) & (Bn - 1);
            const int c  = item >> 10;

            float rre[4], rim[4];
            calc_r(d4, decay, freq, rre, rim);

            const float4* xp = x + (size_t)(b * Tn + c * Ln) * D4n + d4;
            float zre[4] = {0.f, 0.f, 0.f, 0.f};
            float zim[4] = {0.f, 0.f, 0.f, 0.f};
#pragma unroll 8
            for (int j = 0; j < Ln; j++) {
                float4 xv = xp[(size_t)j * D4n];
                float xr[4] = {xv.x, xv.y, xv.z, xv.w};
#pragma unroll
                for (int k = 0; k < 4; k++) {
                    float nre = fmaf(rre[k], zre[k], fmaf(-rim[k], zim[k], xr[k]));
                    float nim = fmaf(rre[k], zim[k], rim[k] * zre[k]);
                    zre[k] = nre;
                    zim[k] = nim;
                }
            }
#pragma unroll
            for (int k = 0; k < 4; k++)
                g_ends[((c * Bn + b) * 4 + k) * D4n + d4] =
                    make_float2(zre[k], zim[k]);
        }
    }

    // ---- table duty: 6144 threads, one double triple each (in barrier slack) ----
    if (t < 6 * Dn) {
        int d = t % Dn;
        int j = t / Dn;                       // 0 -> rL, 1..5 -> w[j-1]
        double span = (j == 0) ? (double)Ln
                               : (double)(CPL * Ln * (1 << (j - 1)));
        double a = fabs((double)decay[d]);
        double f = (double)freq[d];
        double g = exp(-a * span);
        float2 v = make_float2((float)(g * cos(f * span)),
                               (float)(g * sin(f * span)));
        if (j == 0) g_rL[d] = v;
        else        g_w[j - 1][d] = v;
    }

    gsync(0);

    // ---------------- phase 2: warp-parallel scan (static, all warps) ----------------
    {
        const int wid  = t >> 5;         // 0 .. Bn*Dn-1  (4096 series)
        const int lane2 = t & 31;
        const int d  = wid % Dn;
        const int sb = wid / Dn;
        const int sd4 = d >> 2;
        const int sk  = d & 3;

        float2 rL = g_rL[d];
        float rLre = rL.x, rLim = rL.y;

        float2 e[CPL];
        float Are = 0.0f, Aim = 0.0f;
#pragma unroll
        for (int i = 0; i < CPL; i++) {
            int cc = lane2 * CPL + i;
            e[i] = g_ends[((cc * Bn + sb) * 4 + sk) * D4n + sd4];
            float nre = fmaf(rLre, Are, fmaf(-rLim, Aim, e[i].x));
            float nim = fmaf(rLre, Aim, fmaf(rLim, Are, e[i].y));
            Are = nre; Aim = nim;
        }

        float Sre = Are, Sim = Aim;
#pragma unroll
        for (int step = 0; step < 5; step++) {
            int off = 1 << step;
            float2 w = g_w[step][d];
            float Pre = __shfl_up_sync(0xFFFFFFFFu, Sre, off);
            float Pim = __shfl_up_sync(0xFFFFFFFFu, Sim, off);
            if (lane2 >= off) {
                Sre = fmaf(w.x, Pre, fmaf(-w.y, Pim, Sre));
                Sim = fmaf(w.x, Pim, fmaf(w.y, Pre, Sim));
            }
        }

        float Cre = __shfl_up_sync(0xFFFFFFFFu, Sre, 1);
        float Cim = __shfl_up_sync(0xFFFFFFFFu, Sim, 1);
        if (lane2 == 0) { Cre = 0.0f; Cim = 0.0f; }

#pragma unroll
        for (int i = 0; i < CPL; i++) {
            int cc = lane2 * CPL + i;
            g_carry[((cc * Bn + sb) * 4 + sk) * D4n + sd4] =
                make_float2(Cre, Cim);
            float nre = fmaf(rLre, Cre, fmaf(-rLim, Cim, e[i].x));
            float nim = fmaf(rLre, Cim, fmaf(rLim, Cre, e[i].y));
            Cre = nre; Cim = nim;
        }
    }

    gsync(1);

    // -------- phase 3: stolen replay, reverse unit order (x L2-hot first) --------
    {
        unsigned long long tk;
        while (true) {
            if (lane == 0) tk = atomicAdd(&g_work[1], 1ULL);
            tk = __shfl_sync(0xFFFFFFFFu, tk, 0);
            unsigned u = (unsigned)(tk % PERIOD);
            if (u >= NUNITS) break;
            u = (unsigned)(NUNITS - 1) - u;       // reverse: recent chunks first

            const int item = (int)u * 32 + lane;
            const int d4 = item & (D4n - 1);
            const int b  = (item >> 8) & (Bn - 1);
            const int c  = item >> 10;

            float rre[4], rim[4];
            calc_r(d4, decay, freq, rre, rim);

            float zre[4], zim[4];
#pragma unroll
            for (int k = 0; k < 4; k++) {
                float2 cc = g_carry[((c * Bn + b) * 4 + k) * D4n + d4];
                zre[k] = cc.x;
                zim[k] = cc.y;
            }

            const float4* xp = x + (size_t)(b * Tn + c * Ln) * D4n + d4;
            float4*       yp = y + (size_t)(b * Tn + c * Ln) * D4n + d4;
#pragma unroll 8
            for (int j = 0; j < Ln; j++) {
                float4 xv = xp[(size_t)j * D4n];
                float xr[4] = {xv.x, xv.y, xv.z, xv.w};
#pragma unroll
                for (int k = 0; k < 4; k++) {
                    float nre = fmaf(rre[k], zre[k], fmaf(-rim[k], zim[k], xr[k]));
                    float nim = fmaf(rre[k], zim[k], rim[k] * zre[k]);
                    zre[k] = nre;
                    zim[k] = nim;
                }
                __stcs(&yp[(size_t)j * D4n],
                       make_float4(zre[0], zre[1], zre[2], zre[3]));
            }
        }
    }
}

// ---------------------------------------------------------------------------
extern "C" void kernel_launch(void* const* d_in, const int* in_sizes, int n_in,
                              void* d_out, int out_size)
{
    const float* x     = (const float*)d_in[0];
    const float* decay = (const float*)d_in[1];
    const float* freq  = (const float*)d_in[2];
    float* y = (float*)d_out;

    k_fused<<<GRID_CTAS, TPB>>>((const float4*)x, (float4*)y, decay, freq);
}